// round 9
// baseline (speedup 1.0000x reference)
#include <cuda_runtime.h>
#include <cuda_bf16.h>
#include <cstdint>

// ---------------------------------------------------------------------------
// Static scratch (no allocs allowed).
// ---------------------------------------------------------------------------
__device__ float         g_S [4096u * 4096u];   // logits (fp32), 64 MB
__device__ __nv_bfloat16 g_Qh[4096u * 4096u], g_Ql[4096u * 4096u];
__device__ __nv_bfloat16 g_Kh[4096u * 4096u], g_Kl[4096u * 4096u];
__device__ __nv_bfloat16 g_Vh[4096u * 4096u], g_Vl[4096u * 4096u];  // V transposed: Vt[n][k]
__device__ __nv_bfloat16 g_Ph[4096u * 4096u], g_Pl[4096u * 4096u];

#define LDX 12288
#define NQ  4096

// ---------------------------------------------------------------------------
// PTX helpers — base-target only (sm_80-era): cp.async, ldmatrix, mma.sync.
// ---------------------------------------------------------------------------
__device__ __forceinline__ uint32_t smem_u32(const void* p) {
    uint32_t a;
    asm("{ .reg .u64 t; cvta.to.shared.u64 t, %1; cvt.u32.u64 %0, t; }" : "=r"(a) : "l"(p));
    return a;
}
__device__ __forceinline__ void cp_async16(uint32_t s, const void* g) {
    asm volatile("cp.async.cg.shared.global [%0], [%1], 16;" :: "r"(s), "l"(g));
}
#define CP_COMMIT() asm volatile("cp.async.commit_group;" ::: "memory")
#define CP_WAIT0()  asm volatile("cp.async.wait_group 0;" ::: "memory")
#define CP_WAIT1()  asm volatile("cp.async.wait_group 1;" ::: "memory")

__device__ __forceinline__ void ldsm_x4(unsigned* r, uint32_t a) {
    asm volatile("ldmatrix.sync.aligned.m8n8.x4.shared.b16 {%0,%1,%2,%3}, [%4];"
                 : "=r"(r[0]), "=r"(r[1]), "=r"(r[2]), "=r"(r[3]) : "r"(a));
}
__device__ __forceinline__ void mma_bf16(float* c, const unsigned* a, const unsigned* b) {
    asm volatile(
        "mma.sync.aligned.m16n8k16.row.col.f32.bf16.bf16.f32 "
        "{%0,%1,%2,%3}, {%4,%5,%6,%7}, {%8,%9}, {%0,%1,%2,%3};\n"
        : "+f"(c[0]), "+f"(c[1]), "+f"(c[2]), "+f"(c[3])
        : "r"(a[0]), "r"(a[1]), "r"(a[2]), "r"(a[3]), "r"(b[0]), "r"(b[1]));
}

// ---------------------------------------------------------------------------
// Split helpers: fp32 -> bf16 hi + bf16 lo (lo = round(x - hi)).
// ---------------------------------------------------------------------------
__device__ __forceinline__ void split4_store(float4 v, __nv_bfloat16* hi, __nv_bfloat16* lo, size_t idx) {
    __nv_bfloat162 h01, h23, l01, l23;
    h01.x = __float2bfloat16(v.x); h01.y = __float2bfloat16(v.y);
    h23.x = __float2bfloat16(v.z); h23.y = __float2bfloat16(v.w);
    l01.x = __float2bfloat16(v.x - __bfloat162float(h01.x));
    l01.y = __float2bfloat16(v.y - __bfloat162float(h01.y));
    l23.x = __float2bfloat16(v.z - __bfloat162float(h23.x));
    l23.y = __float2bfloat16(v.w - __bfloat162float(h23.y));
    *(__nv_bfloat162*)(hi + idx)     = h01;
    *(__nv_bfloat162*)(hi + idx + 2) = h23;
    *(__nv_bfloat162*)(lo + idx)     = l01;
    *(__nv_bfloat162*)(lo + idx + 2) = l23;
}

__global__ __launch_bounds__(256)
void convert_qk_kernel(const float* __restrict__ x) {
    size_t gid = (size_t)blockIdx.x * 256 + threadIdx.x;   // 4M threads
    int i = (int)(gid >> 10);
    int c = (int)(gid & 1023) << 2;
    float4 q = *(const float4*)(x + (size_t)i * LDX + c);
    float4 k = *(const float4*)(x + (size_t)i * LDX + 4096 + c);
    size_t idx = (size_t)i * NQ + c;
    split4_store(q, g_Qh, g_Ql, idx);
    split4_store(k, g_Kh, g_Kl, idx);
}

// V transpose + split: Vt[n][k] = V[k][n], 32x32 tiles.
__global__ __launch_bounds__(256)
void convert_v_kernel(const float* __restrict__ x) {
    __shared__ float t[32][33];
    int n0 = blockIdx.x * 32, k0 = blockIdx.y * 32;
    int tx = threadIdx.x & 31, ty = threadIdx.x >> 5;
    #pragma unroll
    for (int j = 0; j < 4; j++) {
        int k = k0 + ty + j * 8;
        t[ty + j * 8][tx] = x[(size_t)k * LDX + 8192 + n0 + tx];
    }
    __syncthreads();
    #pragma unroll
    for (int j = 0; j < 4; j++) {
        int n = n0 + ty + j * 8;
        float v = t[tx][ty + j * 8];
        __nv_bfloat16 h = __float2bfloat16(v);
        __nv_bfloat16 l = __float2bfloat16(v - __bfloat162float(h));
        g_Vh[(size_t)n * NQ + k0 + tx] = h;
        g_Vl[(size_t)n * NQ + k0 + tx] = l;
    }
}

// ---------------------------------------------------------------------------
// bf16-split GEMM: out[M,N] = scale * (Ahi+Alo)(Bhi+Blo)^T  (3 products)
// A, B K-major [row][4096]. Tile 128x128, BK=64 (128B rows, XOR-8 swizzle),
// 3-stage cp.async pipeline, 256 threads, 8 warps (warp tile 64x32).
// A and B fragments both via ldmatrix.x4.
// ---------------------------------------------------------------------------
#define ARR_BYTES   16384            // 128 rows x 128 B
#define STAGE_BYTES (4 * ARR_BYTES)  // Ahi|Alo|Bhi|Blo = 64 KB
#define GSMEM_TOTAL (3 * STAGE_BYTES)

__global__ __launch_bounds__(256, 1)
void gemm_bf16_kernel(const __nv_bfloat16* __restrict__ Ah, const __nv_bfloat16* __restrict__ Al,
                      const __nv_bfloat16* __restrict__ Bh, const __nv_bfloat16* __restrict__ Bl,
                      float* __restrict__ out, float scale) {
    extern __shared__ __align__(128) char smem[];
    const uint32_t sb0 = smem_u32(smem);

    const int tid  = threadIdx.x;
    const int warp = tid >> 5;
    const int lane = tid & 31;
    const int bm = blockIdx.y * 128;
    const int bn = blockIdx.x * 128;
    const int wm = (warp >> 2) * 64;
    const int wn = (warp & 3) * 32;
    const int g  = lane >> 2;
    const int tg = lane & 3;

    const __nv_bfloat16* srcs[4] = {Ah, Al, Bh, Bl};

    // producer mapping: 4 x 16B per array per thread
    const int prow = tid >> 3;
    const int pch  = tid & 7;

    auto issue_stage = [&](int c) {
        const int k0 = c << 6;
        const uint32_t st = sb0 + (uint32_t)(c % 3) * STAGE_BYTES;
        #pragma unroll
        for (int arr = 0; arr < 4; arr++) {
            const __nv_bfloat16* src = srcs[arr];
            const int rb = (arr < 2) ? bm : bn;
            const uint32_t ab = st + arr * ARR_BYTES;
            #pragma unroll
            for (int j = 0; j < 4; j++) {
                const int row = prow + j * 32;
                const void* gp = src + (size_t)(rb + row) * NQ + k0 + pch * 8;
                cp_async16(ab + row * 128 + ((pch ^ (row & 7)) * 16), gp);
            }
        }
    };

    float acc[4][4][4];
    #pragma unroll
    for (int i = 0; i < 4; i++)
        #pragma unroll
        for (int j = 0; j < 4; j++)
            #pragma unroll
            for (int r = 0; r < 4; r++) acc[i][j][r] = 0.f;

    // fragment address bases (both A and B use the x4 lane mapping)
    const int l15 = lane & 15;
    const int cs  = lane >> 4;                  // k-chunk select (0/1)
    const int arow = wm + l15;                  // + mi*16
    const uint32_t aoff = (uint32_t)arow * 128;
    const int asw = arow & 7;
    const int brow = wn + l15;                  // + np*16
    const uint32_t boff = (uint32_t)brow * 128;
    const int bsw = brow & 7;

    issue_stage(0); CP_COMMIT();
    issue_stage(1); CP_COMMIT();

    for (int c = 0; c < 64; ++c) {
        if (c < 63) { CP_WAIT1(); } else { CP_WAIT0(); }
        __syncthreads();
        if (c + 2 < 64) { issue_stage(c + 2); CP_COMMIT(); }

        const uint32_t st  = sb0 + (uint32_t)(c % 3) * STAGE_BYTES;
        const uint32_t stB = st + 2 * ARR_BYTES;
        #pragma unroll
        for (int kk = 0; kk < 4; kk++) {
            const uint32_t swzA = (uint32_t)(((kk * 2 + cs) ^ asw) * 16);
            const uint32_t swzB = (uint32_t)(((kk * 2 + cs) ^ bsw) * 16);
            unsigned ah[4][4], al[4][4], bh[4][2], bl[4][2];
            #pragma unroll
            for (int mi = 0; mi < 4; mi++) {
                const uint32_t aA = st + aoff + mi * 2048 + swzA;
                ldsm_x4(ah[mi], aA);
                ldsm_x4(al[mi], aA + ARR_BYTES);
            }
            #pragma unroll
            for (int np = 0; np < 2; np++) {
                const uint32_t aB = stB + boff + np * 2048 + swzB;
                unsigned th[4], tl[4];
                ldsm_x4(th, aB);
                ldsm_x4(tl, aB + ARR_BYTES);
                bh[np * 2][0] = th[0]; bh[np * 2][1] = th[2];
                bh[np * 2 + 1][0] = th[1]; bh[np * 2 + 1][1] = th[3];
                bl[np * 2][0] = tl[0]; bl[np * 2][1] = tl[2];
                bl[np * 2 + 1][0] = tl[1]; bl[np * 2 + 1][1] = tl[3];
            }
            #pragma unroll
            for (int mi = 0; mi < 4; mi++)
                #pragma unroll
                for (int ni = 0; ni < 4; ni++) {
                    mma_bf16(acc[mi][ni], ah[mi], bh[ni]);
                    mma_bf16(acc[mi][ni], ah[mi], bl[ni]);
                    mma_bf16(acc[mi][ni], al[mi], bh[ni]);
                }
        }
    }

    // epilogue
    #pragma unroll
    for (int mi = 0; mi < 4; mi++) {
        #pragma unroll
        for (int ni = 0; ni < 4; ni++) {
            const int row = bm + wm + mi * 16 + g;
            const int col = bn + wn + ni * 8 + tg * 2;
            float2 v0 = { scale * acc[mi][ni][0], scale * acc[mi][ni][1] };
            float2 v1 = { scale * acc[mi][ni][2], scale * acc[mi][ni][3] };
            *(float2*)(out + (size_t)row * NQ + col)       = v0;
            *(float2*)(out + (size_t)(row + 8) * NQ + col) = v1;
        }
    }
}

// ---------------------------------------------------------------------------
// Row softmax: reads g_S fp32, writes P as bf16 hi/lo.
// ---------------------------------------------------------------------------
__global__ __launch_bounds__(256)
void softmax_kernel() {
    const int row = blockIdx.x;
    const float4* p = (const float4*)(g_S + (size_t)row * NQ);
    const int t = threadIdx.x, warp = t >> 5, lane = t & 31;
    __shared__ float red[8];

    float4 v[4];
    float m = -3.4e38f;
    #pragma unroll
    for (int i = 0; i < 4; i++) {
        v[i] = p[t + i * 256];
        m = fmaxf(m, fmaxf(fmaxf(v[i].x, v[i].y), fmaxf(v[i].z, v[i].w)));
    }
    #pragma unroll
    for (int o = 16; o > 0; o >>= 1) m = fmaxf(m, __shfl_xor_sync(0xffffffffu, m, o));
    if (lane == 0) red[warp] = m;
    __syncthreads();
    m = red[0];
    #pragma unroll
    for (int i = 1; i < 8; i++) m = fmaxf(m, red[i]);
    __syncthreads();

    float sum = 0.f;
    #pragma unroll
    for (int i = 0; i < 4; i++) {
        v[i].x = __expf(v[i].x - m); v[i].y = __expf(v[i].y - m);
        v[i].z = __expf(v[i].z - m); v[i].w = __expf(v[i].w - m);
        sum += v[i].x + v[i].y + v[i].z + v[i].w;
    }
    #pragma unroll
    for (int o = 16; o > 0; o >>= 1) sum += __shfl_xor_sync(0xffffffffu, sum, o);
    if (lane == 0) red[warp] = sum;
    __syncthreads();
    sum = red[0];
    #pragma unroll
    for (int i = 1; i < 8; i++) sum += red[i];
    const float inv = 1.f / sum;

    #pragma unroll
    for (int i = 0; i < 4; i++) {
        v[i].x *= inv; v[i].y *= inv; v[i].z *= inv; v[i].w *= inv;
        size_t idx = (size_t)row * NQ + (size_t)(t + i * 256) * 4;
        split4_store(v[i], g_Ph, g_Pl, idx);
    }
}

// ---------------------------------------------------------------------------
extern "C" void kernel_launch(void* const* d_in, const int* in_sizes, int n_in,
                              void* d_out, int out_size) {
    const float* x = (const float*)d_in[0];
    float* out = (float*)d_out;
    (void)in_sizes; (void)n_in; (void)out_size;

    cudaFuncSetAttribute(gemm_bf16_kernel, cudaFuncAttributeMaxDynamicSharedMemorySize, GSMEM_TOTAL);

    void *qh, *ql, *kh, *kl, *vh, *vl, *ph, *pl, *sS;
    cudaGetSymbolAddress(&qh, g_Qh); cudaGetSymbolAddress(&ql, g_Ql);
    cudaGetSymbolAddress(&kh, g_Kh); cudaGetSymbolAddress(&kl, g_Kl);
    cudaGetSymbolAddress(&vh, g_Vh); cudaGetSymbolAddress(&vl, g_Vl);
    cudaGetSymbolAddress(&ph, g_Ph); cudaGetSymbolAddress(&pl, g_Pl);
    cudaGetSymbolAddress(&sS, g_S);

    convert_qk_kernel<<<16384, 256>>>(x);
    convert_v_kernel<<<dim3(128, 128), 256>>>(x);

    dim3 grid(32, 32);
    gemm_bf16_kernel<<<grid, 256, GSMEM_TOTAL>>>(
        (const __nv_bfloat16*)qh, (const __nv_bfloat16*)ql,
        (const __nv_bfloat16*)kh, (const __nv_bfloat16*)kl,
        (float*)sS, 0.5f);

    softmax_kernel<<<4096, 256>>>();

    gemm_bf16_kernel<<<grid, 256, GSMEM_TOTAL>>>(
        (const __nv_bfloat16*)ph, (const __nv_bfloat16*)pl,
        (const __nv_bfloat16*)vh, (const __nv_bfloat16*)vl,
        out, 1.0f);
}

// round 10
// speedup vs baseline: 1.2182x; 1.2182x over previous
#include <cuda_runtime.h>
#include <cuda_bf16.h>
#include <cstdint>

// ---------------------------------------------------------------------------
// Static scratch (no allocs allowed).
// ---------------------------------------------------------------------------
__device__ float         g_S [4096u * 4096u];   // logits (fp32), 64 MB
__device__ __nv_bfloat16 g_Qh[4096u * 4096u], g_Ql[4096u * 4096u];
__device__ __nv_bfloat16 g_Kh[4096u * 4096u], g_Kl[4096u * 4096u];
__device__ __nv_bfloat16 g_Vh[4096u * 4096u], g_Vl[4096u * 4096u];  // V transposed: Vt[n][k]
__device__ __nv_bfloat16 g_Ph[4096u * 4096u], g_Pl[4096u * 4096u];

#define LDX 12288
#define NQ  4096

// ---------------------------------------------------------------------------
// PTX helpers — base-target only (sm_80-era): cp.async, ldmatrix, mma.sync.
// ---------------------------------------------------------------------------
__device__ __forceinline__ uint32_t smem_u32(const void* p) {
    uint32_t a;
    asm("{ .reg .u64 t; cvta.to.shared.u64 t, %1; cvt.u32.u64 %0, t; }" : "=r"(a) : "l"(p));
    return a;
}
__device__ __forceinline__ void cp_async16(uint32_t s, const void* g) {
    asm volatile("cp.async.cg.shared.global [%0], [%1], 16;" :: "r"(s), "l"(g));
}
#define CP_COMMIT() asm volatile("cp.async.commit_group;" ::: "memory")
#define CP_WAIT0()  asm volatile("cp.async.wait_group 0;" ::: "memory")
#define CP_WAIT1()  asm volatile("cp.async.wait_group 1;" ::: "memory")

__device__ __forceinline__ void ldsm_x4(unsigned* r, uint32_t a) {
    asm volatile("ldmatrix.sync.aligned.m8n8.x4.shared.b16 {%0,%1,%2,%3}, [%4];"
                 : "=r"(r[0]), "=r"(r[1]), "=r"(r[2]), "=r"(r[3]) : "r"(a));
}
__device__ __forceinline__ void ldsm_x2(unsigned* r, uint32_t a) {
    asm volatile("ldmatrix.sync.aligned.m8n8.x2.shared.b16 {%0,%1}, [%2];"
                 : "=r"(r[0]), "=r"(r[1]) : "r"(a));
}
__device__ __forceinline__ void mma_bf16(float* c, const unsigned* a, const unsigned* b) {
    asm volatile(
        "mma.sync.aligned.m16n8k16.row.col.f32.bf16.bf16.f32 "
        "{%0,%1,%2,%3}, {%4,%5,%6,%7}, {%8,%9}, {%0,%1,%2,%3};\n"
        : "+f"(c[0]), "+f"(c[1]), "+f"(c[2]), "+f"(c[3])
        : "r"(a[0]), "r"(a[1]), "r"(a[2]), "r"(a[3]), "r"(b[0]), "r"(b[1]));
}

// ---------------------------------------------------------------------------
// Split helpers: fp32 -> bf16 hi + bf16 lo (lo = round(x - hi)).
// ---------------------------------------------------------------------------
__device__ __forceinline__ void split4_store(float4 v, __nv_bfloat16* hi, __nv_bfloat16* lo, size_t idx) {
    __nv_bfloat162 h01, h23, l01, l23;
    h01.x = __float2bfloat16(v.x); h01.y = __float2bfloat16(v.y);
    h23.x = __float2bfloat16(v.z); h23.y = __float2bfloat16(v.w);
    l01.x = __float2bfloat16(v.x - __bfloat162float(h01.x));
    l01.y = __float2bfloat16(v.y - __bfloat162float(h01.y));
    l23.x = __float2bfloat16(v.z - __bfloat162float(h23.x));
    l23.y = __float2bfloat16(v.w - __bfloat162float(h23.y));
    *(__nv_bfloat162*)(hi + idx)     = h01;
    *(__nv_bfloat162*)(hi + idx + 2) = h23;
    *(__nv_bfloat162*)(lo + idx)     = l01;
    *(__nv_bfloat162*)(lo + idx + 2) = l23;
}

__global__ __launch_bounds__(256)
void convert_qk_kernel(const float* __restrict__ x) {
    size_t gid = (size_t)blockIdx.x * 256 + threadIdx.x;   // 4M threads
    int i = (int)(gid >> 10);
    int c = (int)(gid & 1023) << 2;
    float4 q = *(const float4*)(x + (size_t)i * LDX + c);
    float4 k = *(const float4*)(x + (size_t)i * LDX + 4096 + c);
    size_t idx = (size_t)i * NQ + c;
    split4_store(q, g_Qh, g_Ql, idx);
    split4_store(k, g_Kh, g_Kl, idx);
}

// V transpose + split: Vt[n][k] = V[k][n], 32x32 tiles.
__global__ __launch_bounds__(256)
void convert_v_kernel(const float* __restrict__ x) {
    __shared__ float t[32][33];
    int n0 = blockIdx.x * 32, k0 = blockIdx.y * 32;
    int tx = threadIdx.x & 31, ty = threadIdx.x >> 5;
    #pragma unroll
    for (int j = 0; j < 4; j++) {
        int k = k0 + ty + j * 8;
        t[ty + j * 8][tx] = x[(size_t)k * LDX + 8192 + n0 + tx];
    }
    __syncthreads();
    #pragma unroll
    for (int j = 0; j < 4; j++) {
        int n = n0 + ty + j * 8;
        float v = t[tx][ty + j * 8];
        __nv_bfloat16 h = __float2bfloat16(v);
        __nv_bfloat16 l = __float2bfloat16(v - __bfloat162float(h));
        g_Vh[(size_t)n * NQ + k0 + tx] = h;
        g_Vl[(size_t)n * NQ + k0 + tx] = l;
    }
}

// ---------------------------------------------------------------------------
// bf16-split GEMM: out[M,N] = scale * (Ahi+Alo)(Bhi+Blo)^T  (3 products)
// A, B K-major [row][4096]. Tile 128x128, BK=64 (128B rows, XOR-8 swizzle),
// 3-stage cp.async pipeline, 256 threads, 8 warps (warp tile 64x32).
// ---------------------------------------------------------------------------
#define ARR_BYTES   16384            // 128 rows x 128 B
#define STAGE_BYTES (4 * ARR_BYTES)  // Ahi|Alo|Bhi|Blo = 64 KB
#define GSMEM_TOTAL (3 * STAGE_BYTES)

__global__ __launch_bounds__(256, 1)
void gemm_bf16_kernel(const __nv_bfloat16* __restrict__ Ah, const __nv_bfloat16* __restrict__ Al,
                      const __nv_bfloat16* __restrict__ Bh, const __nv_bfloat16* __restrict__ Bl,
                      float* __restrict__ out, float scale) {
    extern __shared__ __align__(128) char smem[];
    const uint32_t sb0 = smem_u32(smem);

    const int tid  = threadIdx.x;
    const int warp = tid >> 5;
    const int lane = tid & 31;
    const int bm = blockIdx.y * 128;
    const int bn = blockIdx.x * 128;
    const int wm = (warp >> 2) * 64;
    const int wn = (warp & 3) * 32;
    const int g  = lane >> 2;
    const int tg = lane & 3;

    const __nv_bfloat16* srcs[4] = {Ah, Al, Bh, Bl};

    // producer mapping: 4 x 16B per array per thread
    const int prow = tid >> 3;
    const int pch  = tid & 7;

    auto issue_stage = [&](int c, uint32_t st) {
        const int k0 = c << 6;
        #pragma unroll
        for (int arr = 0; arr < 4; arr++) {
            const __nv_bfloat16* src = srcs[arr];
            const int rb = (arr < 2) ? bm : bn;
            const uint32_t ab = st + arr * ARR_BYTES;
            #pragma unroll
            for (int j = 0; j < 4; j++) {
                const int row = prow + j * 32;
                const void* gp = src + (size_t)(rb + row) * NQ + k0 + pch * 8;
                cp_async16(ab + row * 128 + ((pch ^ (row & 7)) * 16), gp);
            }
        }
    };

    float acc[4][4][4];
    #pragma unroll
    for (int i = 0; i < 4; i++)
        #pragma unroll
        for (int j = 0; j < 4; j++)
            #pragma unroll
            for (int r = 0; r < 4; r++) acc[i][j][r] = 0.f;

    // fragment address bases (round-8 mapping: A via x4, B via x2)
    const int arow = wm + (lane & 15);          // + mi*16
    const uint32_t aoff = (uint32_t)arow * 128;
    const int asw = arow & 7;
    const int csa = lane >> 4;                  // k-chunk select (0/1)
    const int lb  = lane & 15;
    const int brow = wn + (lb & 7);             // + ni*8
    const uint32_t boff = (uint32_t)brow * 128;
    const int bsw = brow & 7;
    const int csb = lb >> 3;

    issue_stage(0, sb0); CP_COMMIT();
    issue_stage(1, sb0 + STAGE_BYTES); CP_COMMIT();

    uint32_t stC = sb0;                          // consume slot address
    uint32_t stP = sb0 + 2u * STAGE_BYTES;       // produce slot address
    const uint32_t stEnd = sb0 + 3u * STAGE_BYTES;

    for (int c = 0; c < 64; ++c) {
        if (c < 63) { CP_WAIT1(); } else { CP_WAIT0(); }
        __syncthreads();
        if (c + 2 < 64) {
            issue_stage(c + 2, stP); CP_COMMIT();
            stP += STAGE_BYTES; if (stP == stEnd) stP = sb0;
        }

        const uint32_t st = stC;
        stC += STAGE_BYTES; if (stC == stEnd) stC = sb0;
        #pragma unroll
        for (int kk = 0; kk < 4; kk++) {
            const uint32_t swzA = (uint32_t)(((kk * 2 + csa) ^ asw) * 16);
            const uint32_t swzB = (uint32_t)(((kk * 2 + csb) ^ bsw) * 16);
            unsigned ah[4][4], al[4][4], bh[4][2], bl[4][2];
            #pragma unroll
            for (int mi = 0; mi < 4; mi++) {
                const uint32_t aA = st + aoff + mi * 2048 + swzA;
                ldsm_x4(ah[mi], aA);
                ldsm_x4(al[mi], aA + ARR_BYTES);
            }
            #pragma unroll
            for (int ni = 0; ni < 4; ni++) {
                const uint32_t aB = st + 2 * ARR_BYTES + boff + ni * 1024 + swzB;
                ldsm_x2(bh[ni], aB);
                ldsm_x2(bl[ni], aB + ARR_BYTES);
            }
            #pragma unroll
            for (int mi = 0; mi < 4; mi++)
                #pragma unroll
                for (int ni = 0; ni < 4; ni++) {
                    mma_bf16(acc[mi][ni], ah[mi], bh[ni]);
                    mma_bf16(acc[mi][ni], ah[mi], bl[ni]);
                    mma_bf16(acc[mi][ni], al[mi], bh[ni]);
                }
        }
    }

    // epilogue
    #pragma unroll
    for (int mi = 0; mi < 4; mi++) {
        #pragma unroll
        for (int ni = 0; ni < 4; ni++) {
            const int row = bm + wm + mi * 16 + g;
            const int col = bn + wn + ni * 8 + tg * 2;
            float2 v0 = { scale * acc[mi][ni][0], scale * acc[mi][ni][1] };
            float2 v1 = { scale * acc[mi][ni][2], scale * acc[mi][ni][3] };
            *(float2*)(out + (size_t)row * NQ + col)       = v0;
            *(float2*)(out + (size_t)(row + 8) * NQ + col) = v1;
        }
    }
}

// ---------------------------------------------------------------------------
// Row softmax: reads g_S fp32, writes P as bf16 hi/lo.
// ---------------------------------------------------------------------------
__global__ __launch_bounds__(256)
void softmax_kernel() {
    const int row = blockIdx.x;
    const float4* p = (const float4*)(g_S + (size_t)row * NQ);
    const int t = threadIdx.x, warp = t >> 5, lane = t & 31;
    __shared__ float red[8];

    float4 v[4];
    float m = -3.4e38f;
    #pragma unroll
    for (int i = 0; i < 4; i++) {
        v[i] = p[t + i * 256];
        m = fmaxf(m, fmaxf(fmaxf(v[i].x, v[i].y), fmaxf(v[i].z, v[i].w)));
    }
    #pragma unroll
    for (int o = 16; o > 0; o >>= 1) m = fmaxf(m, __shfl_xor_sync(0xffffffffu, m, o));
    if (lane == 0) red[warp] = m;
    __syncthreads();
    m = red[0];
    #pragma unroll
    for (int i = 1; i < 8; i++) m = fmaxf(m, red[i]);
    __syncthreads();

    float sum = 0.f;
    #pragma unroll
    for (int i = 0; i < 4; i++) {
        v[i].x = __expf(v[i].x - m); v[i].y = __expf(v[i].y - m);
        v[i].z = __expf(v[i].z - m); v[i].w = __expf(v[i].w - m);
        sum += v[i].x + v[i].y + v[i].z + v[i].w;
    }
    #pragma unroll
    for (int o = 16; o > 0; o >>= 1) sum += __shfl_xor_sync(0xffffffffu, sum, o);
    if (lane == 0) red[warp] = sum;
    __syncthreads();
    sum = red[0];
    #pragma unroll
    for (int i = 1; i < 8; i++) sum += red[i];
    const float inv = 1.f / sum;

    #pragma unroll
    for (int i = 0; i < 4; i++) {
        v[i].x *= inv; v[i].y *= inv; v[i].z *= inv; v[i].w *= inv;
        size_t idx = (size_t)row * NQ + (size_t)(t + i * 256) * 4;
        split4_store(v[i], g_Ph, g_Pl, idx);
    }
}

// ---------------------------------------------------------------------------
extern "C" void kernel_launch(void* const* d_in, const int* in_sizes, int n_in,
                              void* d_out, int out_size) {
    const float* x = (const float*)d_in[0];
    float* out = (float*)d_out;
    (void)in_sizes; (void)n_in; (void)out_size;

    cudaFuncSetAttribute(gemm_bf16_kernel, cudaFuncAttributeMaxDynamicSharedMemorySize, GSMEM_TOTAL);

    void *qh, *ql, *kh, *kl, *vh, *vl, *ph, *pl, *sS;
    cudaGetSymbolAddress(&qh, g_Qh); cudaGetSymbolAddress(&ql, g_Ql);
    cudaGetSymbolAddress(&kh, g_Kh); cudaGetSymbolAddress(&kl, g_Kl);
    cudaGetSymbolAddress(&vh, g_Vh); cudaGetSymbolAddress(&vl, g_Vl);
    cudaGetSymbolAddress(&ph, g_Ph); cudaGetSymbolAddress(&pl, g_Pl);
    cudaGetSymbolAddress(&sS, g_S);

    convert_qk_kernel<<<16384, 256>>>(x);
    convert_v_kernel<<<dim3(128, 128), 256>>>(x);

    dim3 grid(32, 32);
    gemm_bf16_kernel<<<grid, 256, GSMEM_TOTAL>>>(
        (const __nv_bfloat16*)qh, (const __nv_bfloat16*)ql,
        (const __nv_bfloat16*)kh, (const __nv_bfloat16*)kl,
        (float*)sS, 0.5f);

    softmax_kernel<<<4096, 256>>>();

    gemm_bf16_kernel<<<grid, 256, GSMEM_TOTAL>>>(
        (const __nv_bfloat16*)ph, (const __nv_bfloat16*)pl,
        (const __nv_bfloat16*)vh, (const __nv_bfloat16*)vl,
        out, 1.0f);
}

// round 11
// speedup vs baseline: 1.7959x; 1.4742x over previous
#include <cuda_runtime.h>
#include <cuda_bf16.h>
#include <cuda_fp16.h>
#include <cstdint>

// ---------------------------------------------------------------------------
// Static scratch (no allocs allowed).
// ---------------------------------------------------------------------------
__device__ float         g_S [4096u * 4096u];   // logits (fp32), 64 MB
__device__ __nv_bfloat16 g_Qh[4096u * 4096u], g_Ql[4096u * 4096u];
__device__ __nv_bfloat16 g_Kh[4096u * 4096u], g_Kl[4096u * 4096u];
__device__ __half        g_Vf[4096u * 4096u];   // V transposed fp16: Vt[n][k]
__device__ __half        g_Pf[4096u * 4096u];   // softmax(P) fp16

#define LDX 12288
#define NQ  4096

// ---------------------------------------------------------------------------
// PTX helpers — base-target only (sm_80-era): cp.async, ldmatrix, mma.sync.
// ---------------------------------------------------------------------------
__device__ __forceinline__ uint32_t smem_u32(const void* p) {
    uint32_t a;
    asm("{ .reg .u64 t; cvta.to.shared.u64 t, %1; cvt.u32.u64 %0, t; }" : "=r"(a) : "l"(p));
    return a;
}
__device__ __forceinline__ void cp_async16(uint32_t s, const void* g) {
    asm volatile("cp.async.cg.shared.global [%0], [%1], 16;" :: "r"(s), "l"(g));
}
#define CP_COMMIT() asm volatile("cp.async.commit_group;" ::: "memory")
#define CP_WAIT0()  asm volatile("cp.async.wait_group 0;" ::: "memory")
#define CP_WAIT1()  asm volatile("cp.async.wait_group 1;" ::: "memory")

__device__ __forceinline__ void ldsm_x4(unsigned* r, uint32_t a) {
    asm volatile("ldmatrix.sync.aligned.m8n8.x4.shared.b16 {%0,%1,%2,%3}, [%4];"
                 : "=r"(r[0]), "=r"(r[1]), "=r"(r[2]), "=r"(r[3]) : "r"(a));
}
__device__ __forceinline__ void ldsm_x2(unsigned* r, uint32_t a) {
    asm volatile("ldmatrix.sync.aligned.m8n8.x2.shared.b16 {%0,%1}, [%2];"
                 : "=r"(r[0]), "=r"(r[1]) : "r"(a));
}
__device__ __forceinline__ void mma_bf16(float* c, const unsigned* a, const unsigned* b) {
    asm volatile(
        "mma.sync.aligned.m16n8k16.row.col.f32.bf16.bf16.f32 "
        "{%0,%1,%2,%3}, {%4,%5,%6,%7}, {%8,%9}, {%0,%1,%2,%3};\n"
        : "+f"(c[0]), "+f"(c[1]), "+f"(c[2]), "+f"(c[3])
        : "r"(a[0]), "r"(a[1]), "r"(a[2]), "r"(a[3]), "r"(b[0]), "r"(b[1]));
}
__device__ __forceinline__ void mma_f16(float* c, const unsigned* a, const unsigned* b) {
    asm volatile(
        "mma.sync.aligned.m16n8k16.row.col.f32.f16.f16.f32 "
        "{%0,%1,%2,%3}, {%4,%5,%6,%7}, {%8,%9}, {%0,%1,%2,%3};\n"
        : "+f"(c[0]), "+f"(c[1]), "+f"(c[2]), "+f"(c[3])
        : "r"(a[0]), "r"(a[1]), "r"(a[2]), "r"(a[3]), "r"(b[0]), "r"(b[1]));
}

// ---------------------------------------------------------------------------
// Split helpers: fp32 -> bf16 hi + bf16 lo (lo = round(x - hi)).
// ---------------------------------------------------------------------------
__device__ __forceinline__ void split4_store(float4 v, __nv_bfloat16* hi, __nv_bfloat16* lo, size_t idx) {
    __nv_bfloat162 h01, h23, l01, l23;
    h01.x = __float2bfloat16(v.x); h01.y = __float2bfloat16(v.y);
    h23.x = __float2bfloat16(v.z); h23.y = __float2bfloat16(v.w);
    l01.x = __float2bfloat16(v.x - __bfloat162float(h01.x));
    l01.y = __float2bfloat16(v.y - __bfloat162float(h01.y));
    l23.x = __float2bfloat16(v.z - __bfloat162float(h23.x));
    l23.y = __float2bfloat16(v.w - __bfloat162float(h23.y));
    *(__nv_bfloat162*)(hi + idx)     = h01;
    *(__nv_bfloat162*)(hi + idx + 2) = h23;
    *(__nv_bfloat162*)(lo + idx)     = l01;
    *(__nv_bfloat162*)(lo + idx + 2) = l23;
}

__global__ __launch_bounds__(256)
void convert_qk_kernel(const float* __restrict__ x) {
    size_t gid = (size_t)blockIdx.x * 256 + threadIdx.x;   // 4M threads
    int i = (int)(gid >> 10);
    int c = (int)(gid & 1023) << 2;
    float4 q = *(const float4*)(x + (size_t)i * LDX + c);
    float4 k = *(const float4*)(x + (size_t)i * LDX + 4096 + c);
    size_t idx = (size_t)i * NQ + c;
    split4_store(q, g_Qh, g_Ql, idx);
    split4_store(k, g_Kh, g_Kl, idx);
}

// V transpose to fp16: Vt[n][k] = V[k][n], 32x32 tiles.
__global__ __launch_bounds__(256)
void convert_v_kernel(const float* __restrict__ x) {
    __shared__ float t[32][33];
    int n0 = blockIdx.x * 32, k0 = blockIdx.y * 32;
    int tx = threadIdx.x & 31, ty = threadIdx.x >> 5;
    #pragma unroll
    for (int j = 0; j < 4; j++) {
        int k = k0 + ty + j * 8;
        t[ty + j * 8][tx] = x[(size_t)k * LDX + 8192 + n0 + tx];
    }
    __syncthreads();
    #pragma unroll
    for (int j = 0; j < 4; j++) {
        int n = n0 + ty + j * 8;
        g_Vf[(size_t)n * NQ + k0 + tx] = __float2half(t[tx][ty + j * 8]);
    }
}

// ---------------------------------------------------------------------------
// GEMM1: bf16-split, S = 0.5 * (Qh+Ql)(Kh+Kl)^T (3 products) — round-10 code.
// Tile 128x128, BK=64, 3-stage cp.async, 256 threads, warp tile 64x32.
// ---------------------------------------------------------------------------
#define ARR_BYTES   16384            // 128 rows x 128 B
#define STAGE1_BYTES (4 * ARR_BYTES) // Ahi|Alo|Bhi|Blo = 64 KB
#define G1SMEM (3 * STAGE1_BYTES)

__global__ __launch_bounds__(256, 1)
void gemm_bf16_kernel(const __nv_bfloat16* __restrict__ Ah, const __nv_bfloat16* __restrict__ Al,
                      const __nv_bfloat16* __restrict__ Bh, const __nv_bfloat16* __restrict__ Bl,
                      float* __restrict__ out, float scale) {
    extern __shared__ __align__(128) char smem[];
    const uint32_t sb0 = smem_u32(smem);

    const int tid  = threadIdx.x;
    const int warp = tid >> 5;
    const int lane = tid & 31;
    const int bm = blockIdx.y * 128;
    const int bn = blockIdx.x * 128;
    const int wm = (warp >> 2) * 64;
    const int wn = (warp & 3) * 32;
    const int g  = lane >> 2;
    const int tg = lane & 3;

    const __nv_bfloat16* srcs[4] = {Ah, Al, Bh, Bl};
    const int prow = tid >> 3;
    const int pch  = tid & 7;

    auto issue_stage = [&](int c, uint32_t st) {
        const int k0 = c << 6;
        #pragma unroll
        for (int arr = 0; arr < 4; arr++) {
            const __nv_bfloat16* src = srcs[arr];
            const int rb = (arr < 2) ? bm : bn;
            const uint32_t ab = st + arr * ARR_BYTES;
            #pragma unroll
            for (int j = 0; j < 4; j++) {
                const int row = prow + j * 32;
                const void* gp = src + (size_t)(rb + row) * NQ + k0 + pch * 8;
                cp_async16(ab + row * 128 + ((pch ^ (row & 7)) * 16), gp);
            }
        }
    };

    float acc[4][4][4];
    #pragma unroll
    for (int i = 0; i < 4; i++)
        #pragma unroll
        for (int j = 0; j < 4; j++)
            #pragma unroll
            for (int r = 0; r < 4; r++) acc[i][j][r] = 0.f;

    const int arow = wm + (lane & 15);
    const uint32_t aoff = (uint32_t)arow * 128;
    const int asw = arow & 7;
    const int csa = lane >> 4;
    const int lb  = lane & 15;
    const int brow = wn + (lb & 7);
    const uint32_t boff = (uint32_t)brow * 128;
    const int bsw = brow & 7;
    const int csb = lb >> 3;

    issue_stage(0, sb0); CP_COMMIT();
    issue_stage(1, sb0 + STAGE1_BYTES); CP_COMMIT();

    uint32_t stC = sb0;
    uint32_t stP = sb0 + 2u * STAGE1_BYTES;
    const uint32_t stEnd = sb0 + 3u * STAGE1_BYTES;

    for (int c = 0; c < 64; ++c) {
        if (c < 63) { CP_WAIT1(); } else { CP_WAIT0(); }
        __syncthreads();
        if (c + 2 < 64) {
            issue_stage(c + 2, stP); CP_COMMIT();
            stP += STAGE1_BYTES; if (stP == stEnd) stP = sb0;
        }

        const uint32_t st = stC;
        stC += STAGE1_BYTES; if (stC == stEnd) stC = sb0;
        #pragma unroll
        for (int kk = 0; kk < 4; kk++) {
            const uint32_t swzA = (uint32_t)(((kk * 2 + csa) ^ asw) * 16);
            const uint32_t swzB = (uint32_t)(((kk * 2 + csb) ^ bsw) * 16);
            unsigned ah[4][4], al[4][4], bh[4][2], bl[4][2];
            #pragma unroll
            for (int mi = 0; mi < 4; mi++) {
                const uint32_t aA = st + aoff + mi * 2048 + swzA;
                ldsm_x4(ah[mi], aA);
                ldsm_x4(al[mi], aA + ARR_BYTES);
            }
            #pragma unroll
            for (int ni = 0; ni < 4; ni++) {
                const uint32_t aB = st + 2 * ARR_BYTES + boff + ni * 1024 + swzB;
                ldsm_x2(bh[ni], aB);
                ldsm_x2(bl[ni], aB + ARR_BYTES);
            }
            #pragma unroll
            for (int mi = 0; mi < 4; mi++)
                #pragma unroll
                for (int ni = 0; ni < 4; ni++) {
                    mma_bf16(acc[mi][ni], ah[mi], bh[ni]);
                    mma_bf16(acc[mi][ni], ah[mi], bl[ni]);
                    mma_bf16(acc[mi][ni], al[mi], bh[ni]);
                }
        }
    }

    #pragma unroll
    for (int mi = 0; mi < 4; mi++) {
        #pragma unroll
        for (int ni = 0; ni < 4; ni++) {
            const int row = bm + wm + mi * 16 + g;
            const int col = bn + wn + ni * 8 + tg * 2;
            float2 v0 = { scale * acc[mi][ni][0], scale * acc[mi][ni][1] };
            float2 v1 = { scale * acc[mi][ni][2], scale * acc[mi][ni][3] };
            *(float2*)(out + (size_t)row * NQ + col)       = v0;
            *(float2*)(out + (size_t)(row + 8) * NQ + col) = v1;
        }
    }
}

// ---------------------------------------------------------------------------
// GEMM2: plain fp16, O = P @ Vt^T (single product). Same skeleton, 2 arrays.
// ---------------------------------------------------------------------------
#define STAGE2_BYTES (2 * ARR_BYTES)  // A|B = 32 KB
#define G2SMEM (3 * STAGE2_BYTES)

__global__ __launch_bounds__(256)
void gemm_f16_kernel(const __half* __restrict__ A, const __half* __restrict__ B,
                     float* __restrict__ out) {
    extern __shared__ __align__(128) char smem[];
    const uint32_t sb0 = smem_u32(smem);

    const int tid  = threadIdx.x;
    const int warp = tid >> 5;
    const int lane = tid & 31;
    const int bm = blockIdx.y * 128;
    const int bn = blockIdx.x * 128;
    const int wm = (warp >> 2) * 64;
    const int wn = (warp & 3) * 32;
    const int g  = lane >> 2;
    const int tg = lane & 3;

    const int prow = tid >> 3;
    const int pch  = tid & 7;

    auto issue_stage = [&](int c, uint32_t st) {
        const int k0 = c << 6;
        #pragma unroll
        for (int arr = 0; arr < 2; arr++) {
            const __half* src = (arr == 0) ? A : B;
            const int rb = (arr == 0) ? bm : bn;
            const uint32_t ab = st + arr * ARR_BYTES;
            #pragma unroll
            for (int j = 0; j < 4; j++) {
                const int row = prow + j * 32;
                const void* gp = src + (size_t)(rb + row) * NQ + k0 + pch * 8;
                cp_async16(ab + row * 128 + ((pch ^ (row & 7)) * 16), gp);
            }
        }
    };

    float acc[4][4][4];
    #pragma unroll
    for (int i = 0; i < 4; i++)
        #pragma unroll
        for (int j = 0; j < 4; j++)
            #pragma unroll
            for (int r = 0; r < 4; r++) acc[i][j][r] = 0.f;

    const int arow = wm + (lane & 15);
    const uint32_t aoff = (uint32_t)arow * 128;
    const int asw = arow & 7;
    const int csa = lane >> 4;
    const int lb  = lane & 15;
    const int brow = wn + (lb & 7);
    const uint32_t boff = (uint32_t)brow * 128;
    const int bsw = brow & 7;
    const int csb = lb >> 3;

    issue_stage(0, sb0); CP_COMMIT();
    issue_stage(1, sb0 + STAGE2_BYTES); CP_COMMIT();

    uint32_t stC = sb0;
    uint32_t stP = sb0 + 2u * STAGE2_BYTES;
    const uint32_t stEnd = sb0 + 3u * STAGE2_BYTES;

    for (int c = 0; c < 64; ++c) {
        if (c < 63) { CP_WAIT1(); } else { CP_WAIT0(); }
        __syncthreads();
        if (c + 2 < 64) {
            issue_stage(c + 2, stP); CP_COMMIT();
            stP += STAGE2_BYTES; if (stP == stEnd) stP = sb0;
        }

        const uint32_t st = stC;
        stC += STAGE2_BYTES; if (stC == stEnd) stC = sb0;
        #pragma unroll
        for (int kk = 0; kk < 4; kk++) {
            const uint32_t swzA = (uint32_t)(((kk * 2 + csa) ^ asw) * 16);
            const uint32_t swzB = (uint32_t)(((kk * 2 + csb) ^ bsw) * 16);
            unsigned a[4][4], b[4][2];
            #pragma unroll
            for (int mi = 0; mi < 4; mi++)
                ldsm_x4(a[mi], st + aoff + mi * 2048 + swzA);
            #pragma unroll
            for (int ni = 0; ni < 4; ni++)
                ldsm_x2(b[ni], st + ARR_BYTES + boff + ni * 1024 + swzB);
            #pragma unroll
            for (int mi = 0; mi < 4; mi++)
                #pragma unroll
                for (int ni = 0; ni < 4; ni++)
                    mma_f16(acc[mi][ni], a[mi], b[ni]);
        }
    }

    #pragma unroll
    for (int mi = 0; mi < 4; mi++) {
        #pragma unroll
        for (int ni = 0; ni < 4; ni++) {
            const int row = bm + wm + mi * 16 + g;
            const int col = bn + wn + ni * 8 + tg * 2;
            float2 v0 = { acc[mi][ni][0], acc[mi][ni][1] };
            float2 v1 = { acc[mi][ni][2], acc[mi][ni][3] };
            *(float2*)(out + (size_t)row * NQ + col)       = v0;
            *(float2*)(out + (size_t)(row + 8) * NQ + col) = v1;
        }
    }
}

// ---------------------------------------------------------------------------
// Row softmax: reads g_S fp32, writes P as single fp16.
// ---------------------------------------------------------------------------
__global__ __launch_bounds__(256)
void softmax_kernel() {
    const int row = blockIdx.x;
    const float4* p = (const float4*)(g_S + (size_t)row * NQ);
    const int t = threadIdx.x, warp = t >> 5, lane = t & 31;
    __shared__ float red[8];

    float4 v[4];
    float m = -3.4e38f;
    #pragma unroll
    for (int i = 0; i < 4; i++) {
        v[i] = p[t + i * 256];
        m = fmaxf(m, fmaxf(fmaxf(v[i].x, v[i].y), fmaxf(v[i].z, v[i].w)));
    }
    #pragma unroll
    for (int o = 16; o > 0; o >>= 1) m = fmaxf(m, __shfl_xor_sync(0xffffffffu, m, o));
    if (lane == 0) red[warp] = m;
    __syncthreads();
    m = red[0];
    #pragma unroll
    for (int i = 1; i < 8; i++) m = fmaxf(m, red[i]);
    __syncthreads();

    float sum = 0.f;
    #pragma unroll
    for (int i = 0; i < 4; i++) {
        v[i].x = __expf(v[i].x - m); v[i].y = __expf(v[i].y - m);
        v[i].z = __expf(v[i].z - m); v[i].w = __expf(v[i].w - m);
        sum += v[i].x + v[i].y + v[i].z + v[i].w;
    }
    #pragma unroll
    for (int o = 16; o > 0; o >>= 1) sum += __shfl_xor_sync(0xffffffffu, sum, o);
    if (lane == 0) red[warp] = sum;
    __syncthreads();
    sum = red[0];
    #pragma unroll
    for (int i = 1; i < 8; i++) sum += red[i];
    const float inv = 1.f / sum;

    #pragma unroll
    for (int i = 0; i < 4; i++) {
        size_t idx = (size_t)row * NQ + (size_t)(t + i * 256) * 4;
        __half2 p01, p23;
        p01.x = __float2half(v[i].x * inv); p01.y = __float2half(v[i].y * inv);
        p23.x = __float2half(v[i].z * inv); p23.y = __float2half(v[i].w * inv);
        *(__half2*)(g_Pf + idx)     = p01;
        *(__half2*)(g_Pf + idx + 2) = p23;
    }
}

// ---------------------------------------------------------------------------
extern "C" void kernel_launch(void* const* d_in, const int* in_sizes, int n_in,
                              void* d_out, int out_size) {
    const float* x = (const float*)d_in[0];
    float* out = (float*)d_out;
    (void)in_sizes; (void)n_in; (void)out_size;

    cudaFuncSetAttribute(gemm_bf16_kernel, cudaFuncAttributeMaxDynamicSharedMemorySize, G1SMEM);
    cudaFuncSetAttribute(gemm_f16_kernel,  cudaFuncAttributeMaxDynamicSharedMemorySize, G2SMEM);

    void *qh, *ql, *kh, *kl, *vf, *pf, *sS;
    cudaGetSymbolAddress(&qh, g_Qh); cudaGetSymbolAddress(&ql, g_Ql);
    cudaGetSymbolAddress(&kh, g_Kh); cudaGetSymbolAddress(&kl, g_Kl);
    cudaGetSymbolAddress(&vf, g_Vf); cudaGetSymbolAddress(&pf, g_Pf);
    cudaGetSymbolAddress(&sS, g_S);

    convert_qk_kernel<<<16384, 256>>>(x);
    convert_v_kernel<<<dim3(128, 128), 256>>>(x);

    dim3 grid(32, 32);
    gemm_bf16_kernel<<<grid, 256, G1SMEM>>>(
        (const __nv_bfloat16*)qh, (const __nv_bfloat16*)ql,
        (const __nv_bfloat16*)kh, (const __nv_bfloat16*)kl,
        (float*)sS, 0.5f);

    softmax_kernel<<<4096, 256>>>();

    gemm_f16_kernel<<<grid, 256, G2SMEM>>>(
        (const __half*)pf, (const __half*)vf, out);
}